// round 6
// baseline (speedup 1.0000x reference)
#include <cuda_runtime.h>
#include <cuda_bf16.h>

// Haar wavelet 2x2 transform — dense lanes + MLP=4.
// Input:  x[B=8, C=64, H=512, W=512] fp32
// Output: out[B=8, 4*C=256, H/2=256, W/2=256] fp32
// out channel = 4*c + band, band in {ll, lh, hl, hh}.
//
// One thread = 2 output columns x 2 output rows (h2=2*hp, 2*hp+1):
//   loads  : 4x LDG.128 from input rows 4hp..4hp+3 at dense col 4g
//            (warp-contiguous 512 B per instruction, front-batched MLP=4)
//   stores : 8x STG.64 (2 rows x 4 planes), warp-contiguous 256 B each.

#define B_ 8
#define C_ 64
#define H_ 512
#define W_ 512
#define H2_ (H_ / 2)
#define W2_ (W_ / 2)
#define GROUPS (W2_ / 2)              // 128 two-column groups per output row
#define HPAIRS (H2_ / 2)              // 128 output-row pairs

__global__ __launch_bounds__(256)
void haar_kernel(const float* __restrict__ x, float* __restrict__ out) {
    long long idx = (long long)blockIdx.x * blockDim.x + threadIdx.x;
    // total = B*C*HPAIRS*GROUPS = 8*64*128*128 = 8,388,608
    int g  = (int)(idx & (GROUPS - 1));      // % 128
    long long t = idx >> 7;
    int hp = (int)(t & (HPAIRS - 1));        // % 128
    t >>= 7;
    int c  = (int)(t & (C_ - 1));            // % 64
    int b  = (int)(t >> 6);

    const long long in_plane = (long long)(b * C_ + c) * (H_ * W_);
    const long long in_base  = in_plane + (long long)(4 * hp) * W_ + 4LL * g;

    // 4 independent dense loads (input rows 4hp .. 4hp+3)
    float4 r0 = *reinterpret_cast<const float4*>(x + in_base);
    float4 r1 = *reinterpret_cast<const float4*>(x + in_base + W_);
    float4 r2 = *reinterpret_cast<const float4*>(x + in_base + 2 * W_);
    float4 r3 = *reinterpret_cast<const float4*>(x + in_base + 3 * W_);

    // Output row 2hp from (r0, r1); output row 2hp+1 from (r2, r3).
    // Column 0: pair (.x,.y); column 1: pair (.z,.w).
    float2 ll0, lh0, hl0, hh0, ll1, lh1, hl1, hh1;
    {
        float s0x = r0.x + r0.y, s0z = r0.z + r0.w;
        float s1x = r1.x + r1.y, s1z = r1.z + r1.w;
        float d0x = r0.y - r0.x, d0z = r0.w - r0.z;
        float d1x = r1.y - r1.x, d1z = r1.w - r1.z;
        ll0 = make_float2(0.5f * (s0x + s1x), 0.5f * (s0z + s1z));
        lh0 = make_float2(0.5f * (s1x - s0x), 0.5f * (s1z - s0z));
        hl0 = make_float2(0.5f * (d0x + d1x), 0.5f * (d0z + d1z));
        hh0 = make_float2(0.5f * (d1x - d0x), 0.5f * (d1z - d0z));
    }
    {
        float s0x = r2.x + r2.y, s0z = r2.z + r2.w;
        float s1x = r3.x + r3.y, s1z = r3.z + r3.w;
        float d0x = r2.y - r2.x, d0z = r2.w - r2.z;
        float d1x = r3.y - r3.x, d1z = r3.w - r3.z;
        ll1 = make_float2(0.5f * (s0x + s1x), 0.5f * (s0z + s1z));
        lh1 = make_float2(0.5f * (s1x - s0x), 0.5f * (s1z - s0z));
        hl1 = make_float2(0.5f * (d0x + d1x), 0.5f * (d0z + d1z));
        hh1 = make_float2(0.5f * (d1x - d0x), 0.5f * (d1z - d0z));
    }

    const long long out_row0 =
        ((long long)(b * (4 * C_) + 4 * c) * H2_ + 2 * hp) * W2_ + 2LL * g;
    const long long out_row1 = out_row0 + W2_;
    const long long ps = (long long)H2_ * W2_;   // plane stride

    *reinterpret_cast<float2*>(out + out_row0)          = ll0;
    *reinterpret_cast<float2*>(out + out_row1)          = ll1;
    *reinterpret_cast<float2*>(out + out_row0 + ps)     = lh0;
    *reinterpret_cast<float2*>(out + out_row1 + ps)     = lh1;
    *reinterpret_cast<float2*>(out + out_row0 + 2 * ps) = hl0;
    *reinterpret_cast<float2*>(out + out_row1 + 2 * ps) = hl1;
    *reinterpret_cast<float2*>(out + out_row0 + 3 * ps) = hh0;
    *reinterpret_cast<float2*>(out + out_row1 + 3 * ps) = hh1;
}

extern "C" void kernel_launch(void* const* d_in, const int* in_sizes, int n_in,
                              void* d_out, int out_size) {
    const float* x = (const float*)d_in[0];
    float* out = (float*)d_out;
    const long long total_threads = (long long)B_ * C_ * HPAIRS * GROUPS; // 8,388,608
    const int threads = 256;
    const int blocks = (int)(total_threads / threads);                     // 32768
    haar_kernel<<<blocks, threads>>>(x, out);
}

// round 7
// speedup vs baseline: 1.0026x; 1.0026x over previous
#include <cuda_runtime.h>
#include <cuda_bf16.h>

// Haar wavelet 2x2 transform — R5 dense-lane shape + write-through stores.
// Input:  x[B=8, C=64, H=512, W=512] fp32
// Output: out[B=8, 4*C=256, H/2=256, W/2=256] fp32
// out channel = 4*c + band, band in {ll, lh, hl, hh}.
//
// One thread = 2 output columns (1 float2 per plane):
//   loads  : LDG.128 lane-dense (512 B contiguous per warp per instruction)
//   stores : STG.64.WT lane-dense (256 B contiguous per warp per instruction),
//            write-through — no dirty-L2 eviction bursts against read fills.

#define B_ 8
#define C_ 64
#define H_ 512
#define W_ 512
#define H2_ (H_ / 2)
#define W2_ (W_ / 2)
#define GROUPS (W2_ / 2)              // 128 two-column groups per output row

__global__ __launch_bounds__(256)
void haar_kernel(const float* __restrict__ x, float* __restrict__ out) {
    long long idx = (long long)blockIdx.x * blockDim.x + threadIdx.x;
    // total = B*C*H2*GROUPS = 8*64*256*128 = 16,777,216
    int g  = (int)(idx & (GROUPS - 1));     // % 128
    long long t = idx >> 7;
    int h2 = (int)(t & (H2_ - 1));          // % 256
    t >>= 8;
    int c  = (int)(t & (C_ - 1));           // % 64
    int b  = (int)(t >> 6);

    const long long in_plane = (long long)(b * C_ + c) * (H_ * W_);
    const long long in_row0  = in_plane + (long long)(2 * h2) * W_ + 4LL * g;
    const long long in_row1  = in_row0 + W_;

    float4 r0 = *reinterpret_cast<const float4*>(x + in_row0);
    float4 r1 = *reinterpret_cast<const float4*>(x + in_row1);

    // Column j=0: pair (r.x, r.y); column j=1: pair (r.z, r.w)
    float s0x = r0.x + r0.y,  s0z = r0.z + r0.w;   // row0 sums
    float s1x = r1.x + r1.y,  s1z = r1.z + r1.w;   // row1 sums
    float d0x = r0.y - r0.x,  d0z = r0.w - r0.z;   // row0 diffs
    float d1x = r1.y - r1.x,  d1z = r1.w - r1.z;   // row1 diffs

    float2 ll = make_float2(0.5f * (s0x + s1x), 0.5f * (s0z + s1z));
    float2 lh = make_float2(0.5f * (s1x - s0x), 0.5f * (s1z - s0z));
    float2 hl = make_float2(0.5f * (d0x + d1x), 0.5f * (d0z + d1z));
    float2 hh = make_float2(0.5f * (d1x - d0x), 0.5f * (d1z - d0z));

    const long long out_base =
        ((long long)(b * (4 * C_) + 4 * c) * H2_ + h2) * W2_ + 2LL * g;
    const long long ps = (long long)H2_ * W2_;   // plane stride

    __stwt(reinterpret_cast<float2*>(out + out_base),          ll);
    __stwt(reinterpret_cast<float2*>(out + out_base + ps),     lh);
    __stwt(reinterpret_cast<float2*>(out + out_base + 2 * ps), hl);
    __stwt(reinterpret_cast<float2*>(out + out_base + 3 * ps), hh);
}

extern "C" void kernel_launch(void* const* d_in, const int* in_sizes, int n_in,
                              void* d_out, int out_size) {
    const float* x = (const float*)d_in[0];
    float* out = (float*)d_out;
    const long long total_threads = (long long)B_ * C_ * H2_ * GROUPS; // 16,777,216
    const int threads = 256;
    const int blocks = (int)(total_threads / threads);                  // 65536
    haar_kernel<<<blocks, threads>>>(x, out);
}

// round 8
// speedup vs baseline: 1.0082x; 1.0055x over previous
#include <cuda_runtime.h>
#include <cuda_bf16.h>

// Haar wavelet 2x2 transform — champion R5 shape, 128-thread CTAs.
// Input:  x[B=8, C=64, H=512, W=512] fp32
// Output: out[B=8, 4*C=256, H/2=256, W/2=256] fp32
// out channel = 4*c + band, band in {ll, lh, hl, hh}.
//
// One thread = 2 output columns (1 float2 per plane):
//   loads  : LDG.128 lane-dense (512 B contiguous per warp per instruction)
//   stores : STG.64 lane-dense (256 B contiguous per warp per instruction)
// Every memory instruction touches each 128B line exactly once.

#define B_ 8
#define C_ 64
#define H_ 512
#define W_ 512
#define H2_ (H_ / 2)
#define W2_ (W_ / 2)
#define GROUPS (W2_ / 2)              // 128 two-column groups per output row
#define NTHREADS 128

__global__ __launch_bounds__(NTHREADS)
void haar_kernel(const float* __restrict__ x, float* __restrict__ out) {
    long long idx = (long long)blockIdx.x * NTHREADS + threadIdx.x;
    // total = B*C*H2*GROUPS = 8*64*256*128 = 16,777,216
    int g  = (int)(idx & (GROUPS - 1));     // % 128
    long long t = idx >> 7;
    int h2 = (int)(t & (H2_ - 1));          // % 256
    t >>= 8;
    int c  = (int)(t & (C_ - 1));           // % 64
    int b  = (int)(t >> 6);

    const long long in_plane = (long long)(b * C_ + c) * (H_ * W_);
    const long long in_row0  = in_plane + (long long)(2 * h2) * W_ + 4LL * g;
    const long long in_row1  = in_row0 + W_;

    float4 r0 = *reinterpret_cast<const float4*>(x + in_row0);
    float4 r1 = *reinterpret_cast<const float4*>(x + in_row1);

    // Column j=0: pair (r.x, r.y); column j=1: pair (r.z, r.w)
    float s0x = r0.x + r0.y,  s0z = r0.z + r0.w;   // row0 sums
    float s1x = r1.x + r1.y,  s1z = r1.z + r1.w;   // row1 sums
    float d0x = r0.y - r0.x,  d0z = r0.w - r0.z;   // row0 diffs
    float d1x = r1.y - r1.x,  d1z = r1.w - r1.z;   // row1 diffs

    float2 ll = make_float2(0.5f * (s0x + s1x), 0.5f * (s0z + s1z));
    float2 lh = make_float2(0.5f * (s1x - s0x), 0.5f * (s1z - s0z));
    float2 hl = make_float2(0.5f * (d0x + d1x), 0.5f * (d0z + d1z));
    float2 hh = make_float2(0.5f * (d1x - d0x), 0.5f * (d1z - d0z));

    const long long out_base =
        ((long long)(b * (4 * C_) + 4 * c) * H2_ + h2) * W2_ + 2LL * g;
    const long long ps = (long long)H2_ * W2_;   // plane stride

    *reinterpret_cast<float2*>(out + out_base)          = ll;
    *reinterpret_cast<float2*>(out + out_base + ps)     = lh;
    *reinterpret_cast<float2*>(out + out_base + 2 * ps) = hl;
    *reinterpret_cast<float2*>(out + out_base + 3 * ps) = hh;
}

extern "C" void kernel_launch(void* const* d_in, const int* in_sizes, int n_in,
                              void* d_out, int out_size) {
    const float* x = (const float*)d_in[0];
    float* out = (float*)d_out;
    const long long total_threads = (long long)B_ * C_ * H2_ * GROUPS; // 16,777,216
    const int blocks = (int)(total_threads / NTHREADS);                 // 131072
    haar_kernel<<<blocks, NTHREADS>>>(x, out);
}